// round 15
// baseline (speedup 1.0000x reference)
#include <cuda_runtime.h>
#include <cuda_bf16.h>
#include <cstdint>

// LMN layer, round 15:
//   (1) prologue moved to HMMA too: pack x -> B-frag layout (g_px), pack Wxh
//       slice per CTA -> A-frag smem, 3-term bf16-split mma, write g_xWT.
//       Replaces the L1-bound SIMT prologue (2.1 ms -> ~0.5 ms) + transpose.
//   (2) recur: post-phase2 FULL barrier replaced by partner-flag wait
//       (reduce2 only needs g_partB from CTAs {b, b^1}); out[t] store moved
//       after the final arrive to overlap the wait. Seq advances by 3/step.
// Layouts identical to round 14 (passed, rel_err 2.6e-5).

#define T_STEPS 512
#define DIM     1024
#define STEP    (64 * 1024)
#define OUTS    ((size_t)T_STEPS * STEP)

typedef unsigned long long ull;
typedef uint32_t u32;
typedef uint16_t u16;

__device__ __align__(256) u32   g_px[(size_t)T_STEPS * 65536]; // x packed B-frag
__device__ __align__(256) float g_xWT[(size_t)T_STEPS * STEP]; // [t][feat][batch]
__device__ __align__(256) u32   g_pm[65536];    // m packed [s][nf][pair][lane][4]
__device__ __align__(256) u32   g_ph[65536];    // h packed, same layout
__device__ __align__(256) float g_c2[1024 * 64];
__device__ __align__(256) float g_partB[128 * 16 * 64];
__device__ __align__(128) unsigned g_flags[128 * 32];

// ---------------- bf16 helpers ----------------------------------------------
__device__ __forceinline__ u32 b16(float x) {
    return (u32)__bfloat16_as_ushort(__float2bfloat16(x));
}
__device__ __forceinline__ float fb16(u32 b) {
    return __bfloat162float(__ushort_as_bfloat16((u16)b));
}
__device__ __forceinline__ u32 packlo(float a, float b) {
    float la = a - fb16(b16(a)), lb = b - fb16(b16(b));
    return b16(la) | (b16(lb) << 16);
}
__device__ __forceinline__ u32 packhi(float a, float b) {
    return b16(a) | (b16(b) << 16);
}

// packed activation index: [s][nf][pair(32)][lane(32)][4 u32]
__device__ __forceinline__ size_t pk(int s, int nf, int pair, int lane) {
    return ((((size_t)s * 8 + nf) * 32 + pair) * 32 + lane) * 4;
}

__device__ __forceinline__ void mma4(float* c, const u32* a, u32 b0, u32 b1) {
    asm volatile(
        "mma.sync.aligned.m16n8k16.row.col.f32.bf16.bf16.f32 "
        "{%0,%1,%2,%3}, {%4,%5,%6,%7}, {%8,%9}, {%0,%1,%2,%3};"
        : "+f"(c[0]), "+f"(c[1]), "+f"(c[2]), "+f"(c[3])
        : "r"(a[0]), "r"(a[1]), "r"(a[2]), "r"(a[3]), "r"(b0), "r"(b1));
}

// ---------------- flag-array barrier (128 co-resident CTAs) -----------------
__device__ __forceinline__ void bar_arrive_seq(int b, unsigned seq)
{
    __syncthreads();
    __threadfence();
    if (threadIdx.x == 0)
        asm volatile("st.release.gpu.u32 [%0], %1;"
                     :: "l"(g_flags + (size_t)b * 32), "r"(seq) : "memory");
}
__device__ __forceinline__ void bar_wait_seq(unsigned seq)
{
    if (threadIdx.x < 128) {
        const unsigned* p = g_flags + (size_t)threadIdx.x * 32;
        unsigned v;
        asm volatile("ld.acquire.gpu.u32 %0, [%1];" : "=r"(v) : "l"(p));
        while ((int)(v - seq) < 0) {
            __nanosleep(64);
            asm volatile("ld.acquire.gpu.u32 %0, [%1];" : "=r"(v) : "l"(p));
        }
    }
    __syncthreads();
}
// wait for ONE specific CTA's flag (partner) — cheap
__device__ __forceinline__ void partner_wait_seq(int bq, unsigned seq)
{
    if (threadIdx.x == 0) {
        const unsigned* p = g_flags + (size_t)bq * 32;
        unsigned v;
        asm volatile("ld.acquire.gpu.u32 %0, [%1];" : "=r"(v) : "l"(p));
        while ((int)(v - seq) < 0) {
            __nanosleep(32);
            asm volatile("ld.acquire.gpu.u32 %0, [%1];" : "=r"(v) : "l"(p));
        }
    }
    __syncthreads();
}
__global__ void zero_flags_k() {
    if (threadIdx.x < 128) g_flags[(size_t)threadIdx.x * 32] = 0u;
}

// ---------------- x -> packed B-frag layout (per t) --------------------------
__global__ void __launch_bounds__(512) pack_x_k(const float* __restrict__ x)
{
    const int t = blockIdx.y;
    int e = blockIdx.x * 512 + threadIdx.x;          // 0..65535
    int q = e & 3, lane = (e >> 2) & 31, pair = (e >> 7) & 31;
    int nf = (e >> 12) & 7, s = e >> 15;
    int kf = 2 * pair + (q >> 1), reg = q & 1;
    int kc = 16 * kf + 2 * (lane & 3) + 8 * reg;
    int n  = 8 * nf + (lane >> 2);
    const float* xs = x + (size_t)t * STEP + (size_t)n * DIM + kc;
    float w0 = xs[0], w1 = xs[1];
    g_px[(size_t)t * 65536 + e] = s ? packlo(w0, w1) : packhi(w0, w1);
}

// ---------------- m0 -> packed B-frag layout --------------------------------
__global__ void conv_m0_k(const float* __restrict__ m_prev)
{
    int e = blockIdx.x * 512 + threadIdx.x;
    int q = e & 3, lane = (e >> 2) & 31, pair = (e >> 7) & 31;
    int nf = (e >> 12) & 7, s = e >> 15;
    int kf = 2 * pair + (q >> 1), reg = q & 1;
    int kc = 16 * kf + 2 * (lane & 3) + 8 * reg;
    int n  = 8 * nf + (lane >> 2);
    float w0 = m_prev[(size_t)n * DIM + kc];
    float w1 = m_prev[(size_t)n * DIM + kc + 1];
    g_pm[e] = s ? packlo(w0, w1) : packhi(w0, w1);
}

// ---------------- HMMA prologue: g_xWT[t] = Wxh @ x[t]^T + bh ---------------
// grid (32 Mtiles of 32 rows, 64 t-groups of 8). 512 thr = 8 nf x 2 kh.
#define P_PAH 0
#define P_PAL 16384
#define P_DRED 32768
#define P_SBH (32768 + 2048)
#define PRO_SMEM ((32768 + 2048 + 32) * 4)     // 139392 B

__global__ void __launch_bounds__(512, 1)
prologue_mma_k(const float* __restrict__ Wxh, const float* __restrict__ bh)
{
    extern __shared__ u32 smu[];
    u32*   pah  = smu + P_PAH;
    u32*   pal  = smu + P_PAL;
    float* dred = (float*)(smu + P_DRED);
    float* sbh  = (float*)(smu + P_SBH);

    const int j = blockIdx.x, tid = threadIdx.x;
    const int wid = tid >> 5, lane = tid & 31;
    const int nf = wid & 7, kh = wid >> 3;
    const int gid = lane >> 2, tig = lane & 3;
    const int n0 = 8 * nf + 2 * tig;

    // pack A (Wxh rows 32j..32j+31) into frag order [fr][kf][lane][4]
    for (int e = tid; e < 16384; e += 512) {
        int reg = e & 3, ln = (e >> 2) & 31, kf = (e >> 7) & 63, fr = e >> 13;
        int row_l = 16 * fr + (ln >> 2) + 8 * (reg & 1);
        int kc    = 16 * kf + 2 * (ln & 3) + 8 * (reg >> 1);
        const float* Ws = Wxh + (size_t)(32 * j + row_l) * DIM + kc;
        float w0 = Ws[0], w1 = Ws[1];
        pah[e] = packhi(w0, w1);
        pal[e] = packlo(w0, w1);
    }
    if (tid < 32) sbh[tid] = bh[32 * j + tid];
    __syncthreads();

    #pragma unroll 1
    for (int tt = 0; tt < 8; ++tt) {
        const int t = blockIdx.y * 8 + tt;
        float c2[2][4] = {{0.f,0.f,0.f,0.f},{0.f,0.f,0.f,0.f}};
        {
            const u32* bhp = g_px + (size_t)t * 65536 + pk(0, nf, 16 * kh, lane);
            const u32* blp = g_px + (size_t)t * 65536 + pk(1, nf, 16 * kh, lane);
            #pragma unroll 2
            for (int p = 0; p < 16; ++p) {
                uint4 Bh = *(const uint4*)(bhp + p * 128);
                uint4 Bl = *(const uint4*)(blp + p * 128);
                int kf0 = 32 * kh + 2 * p;
                #pragma unroll
                for (int half = 0; half < 2; ++half) {
                    u32 bh0 = half ? Bh.z : Bh.x, bh1 = half ? Bh.w : Bh.y;
                    u32 bl0 = half ? Bl.z : Bl.x, bl1 = half ? Bl.w : Bl.y;
                    int kf = kf0 + half;
                    #pragma unroll
                    for (int fr = 0; fr < 2; ++fr) {
                        int ab = ((fr * 64 + kf) * 32 + lane) * 4;
                        u32 Ah[4], Al[4];
                        *(uint4*)Ah = *(const uint4*)(pah + ab);
                        *(uint4*)Al = *(const uint4*)(pal + ab);
                        mma4(c2[fr], Ah, bh0, bh1);
                        mma4(c2[fr], Ah, bl0, bl1);
                        mma4(c2[fr], Al, bh0, bh1);
                    }
                }
            }
        }
        // cross-kh reduce through smem
        if (kh == 1) {
            #pragma unroll
            for (int fr = 0; fr < 2; ++fr)
                *(float4*)&dred[(size_t)((nf * 2 + fr) * 32 + lane) * 4] =
                    *(float4*)c2[fr];
        }
        __syncthreads();
        if (kh == 0) {
            #pragma unroll
            for (int fr = 0; fr < 2; ++fr) {
                float4 o = *(float4*)&dred[(size_t)((nf * 2 + fr) * 32 + lane) * 4];
                float v0 = c2[fr][0] + o.x, v1 = c2[fr][1] + o.y;
                float v2 = c2[fr][2] + o.z, v3 = c2[fr][3] + o.w;
                int rl0 = 16 * fr + gid, rl1 = rl0 + 8;
                int r0 = 32 * j + rl0, r1 = 32 * j + rl1;
                *(float2*)(g_xWT + (size_t)t * STEP + (size_t)r0 * 64 + n0) =
                    make_float2(v0 + sbh[rl0], v1 + sbh[rl0]);
                *(float2*)(g_xWT + (size_t)t * STEP + (size_t)r1 * 64 + n0) =
                    make_float2(v2 + sbh[rl1], v3 + sbh[rl1]);
            }
        }
        __syncthreads();
    }
}

// ---------------- persistent HMMA recurrence --------------------------------
#define SM_W1H 0
#define SM_W1L 8192
#define SM_W2H 16384
#define SM_W2L 20480
#define SM_DRED 24576
#define SM_RP  25600
#define TC_SMEM ((25600 + 1152) * 4)     // 107008 B

__global__ void __launch_bounds__(512, 1)
recur_k(const float* __restrict__ Whm, const float* __restrict__ Wmm,
        const float* __restrict__ Wmh, const float* __restrict__ bm,
        float* __restrict__ out)
{
    extern __shared__ u32 smu[];
    u32*   w1h  = smu + SM_W1H;
    u32*   w1l  = smu + SM_W1L;
    u32*   w2h  = smu + SM_W2H;
    u32*   w2l  = smu + SM_W2L;
    float* dred = (float*)(smu + SM_DRED);
    u16*   rp   = (u16*)(smu + SM_RP);   // [s][16][72]

    const int b = blockIdx.x, tid = threadIdx.x;
    const int wid = tid >> 5, lane = tid & 31;
    const int gid = lane >> 2, tig = lane & 3;
    const int nf = wid & 7, kh = wid >> 3;

    // ---- pack W1 (A-frag order) ----
    for (int e = tid; e < 8192; e += 512) {
        int kf = e >> 7, ln = (e >> 2) & 31, reg = e & 3;
        int row_l = (ln >> 2) + 8 * (reg & 1);
        int kc    = 16 * kf + 2 * (ln & 3) + 8 * (reg >> 1);
        const float* Ws = (b < 64)
            ? (Wmh + (size_t)(16 * b + row_l) * DIM)
            : (Wmm + (size_t)(16 * (b - 64) + row_l) * DIM);
        float w0 = Ws[kc], w1 = Ws[kc + 1];
        w1h[e] = packhi(w0, w1);
        w1l[e] = packlo(w0, w1);
    }
    // ---- pack W2: rows 16*(b>>1), k-half (b&1) ----
    for (int e = tid; e < 4096; e += 512) {
        int kfl = e >> 7, ln = (e >> 2) & 31, reg = e & 3;
        int row_g = 16 * (b >> 1) + (ln >> 2) + 8 * (reg & 1);
        int kc    = 512 * (b & 1) + 16 * kfl + 2 * (ln & 3) + 8 * (reg >> 1);
        float w0 = Whm[(size_t)row_g * DIM + kc];
        float w1 = Whm[(size_t)row_g * DIM + kc + 1];
        w2h[e] = packhi(w0, w1);
        w2l[e] = packlo(w0, w1);
    }
    __syncthreads();

    const int n0 = 8 * nf + 2 * tig;

    // hoisted reduce2 constants (tid < 256 lanes)
    const int tg2 = tid >> 6, nn = tid & 63;
    const int rr0 = 2 * tg2;
    const int r0g = 8 * b + rr0, r1g = r0g + 1;
    float bmv0 = 0.f, bmv1 = 0.f;
    if (tid < 256) { bmv0 = bm[r0g]; bmv1 = bm[r1g]; }

    #pragma unroll 1
    for (int t = 0; t < T_STEPS; ++t) {
        // ================= phase 1: D = W1 @ m^T (full K) ==================
        float c[4] = {0.f, 0.f, 0.f, 0.f};
        {
            const u32* bhp = g_pm + pk(0, nf, 16 * kh, lane);
            const u32* blp = g_pm + pk(1, nf, 16 * kh, lane);
            uint4 Bh = *(const uint4*)bhp;
            uint4 Bl = *(const uint4*)blp;
            #pragma unroll 2
            for (int p = 0; p < 16; ++p) {
                uint4 cBh = Bh, cBl = Bl;
                if (p < 15) {
                    Bh = *(const uint4*)(bhp + (p + 1) * 128);
                    Bl = *(const uint4*)(blp + (p + 1) * 128);
                }
                int kf0 = 32 * kh + 2 * p;
                u32 Ah0[4], Ah1[4], Al0[4], Al1[4];
                *(uint4*)Ah0 = *(const uint4*)(w1h + ((size_t)kf0 * 32 + lane) * 4);
                *(uint4*)Ah1 = *(const uint4*)(w1h + ((size_t)(kf0 + 1) * 32 + lane) * 4);
                *(uint4*)Al0 = *(const uint4*)(w1l + ((size_t)kf0 * 32 + lane) * 4);
                *(uint4*)Al1 = *(const uint4*)(w1l + ((size_t)(kf0 + 1) * 32 + lane) * 4);
                mma4(c, Ah0, cBh.x, cBh.y);
                mma4(c, Ah0, cBl.x, cBl.y);
                mma4(c, Al0, cBh.x, cBh.y);
                mma4(c, Ah1, cBh.z, cBh.w);
                mma4(c, Ah1, cBl.z, cBl.w);
                mma4(c, Al1, cBh.z, cBh.w);
            }
        }
        if (wid >= 8)
            *(float4*)&dred[(size_t)((wid - 8) * 32 + lane) * 4] = *(float4*)c;
        __syncthreads();
        if (wid < 8) {
            float4 o = *(float4*)&dred[(size_t)(wid * 32 + lane) * 4];
            c[0] += o.x; c[1] += o.y; c[2] += o.z; c[3] += o.w;
            if (b < 64) {
                int f0 = 16 * b + gid;
                ull xa = *(const ull*)(g_xWT + (size_t)t * STEP
                                       + (size_t)f0 * 64 + n0);
                ull xb = *(const ull*)(g_xWT + (size_t)t * STEP
                                       + (size_t)(f0 + 8) * 64 + n0);
                float h0 = tanhf(c[0] + __uint_as_float((u32)xa));
                float h1 = tanhf(c[1] + __uint_as_float((u32)(xa >> 32)));
                float h2 = tanhf(c[2] + __uint_as_float((u32)xb));
                float h3 = tanhf(c[3] + __uint_as_float((u32)(xb >> 32)));
                *(u32*)&rp[(0 * 16 + gid)     * 72 + n0] = packhi(h0, h1);
                *(u32*)&rp[(0 * 16 + gid + 8) * 72 + n0] = packhi(h2, h3);
                *(u32*)&rp[(1 * 16 + gid)     * 72 + n0] = packlo(h0, h1);
                *(u32*)&rp[(1 * 16 + gid + 8) * 72 + n0] = packlo(h2, h3);
            } else {
                int f0 = 16 * (b - 64) + gid;
                *(float2*)(g_c2 + (size_t)f0 * 64 + n0)       =
                    make_float2(c[0], c[1]);
                *(float2*)(g_c2 + (size_t)(f0 + 8) * 64 + n0) =
                    make_float2(c[2], c[3]);
            }
        }
        __syncthreads();
        if (b < 64) {            // repack h -> g_ph (B-frag layout)
            int s  = tid >> 8, q8 = tid & 255;
            int nf2 = q8 >> 5, ln2 = q8 & 31;
            int np = 8 * nf2 + (ln2 >> 2), tg = ln2 & 3;
            u32 v0 = (u32)rp[(s * 16 + 2 * tg)     * 72 + np]
                   | ((u32)rp[(s * 16 + 2 * tg + 1) * 72 + np] << 16);
            u32 v1 = (u32)rp[(s * 16 + 2 * tg + 8) * 72 + np]
                   | ((u32)rp[(s * 16 + 2 * tg + 9) * 72 + np] << 16);
            ull V = (ull)v0 | ((ull)v1 << 32);
            *(ull*)&g_ph[pk(s, nf2, b >> 1, ln2) + (size_t)(b & 1) * 2] = V;
        }
        bar_arrive_seq(b, 3 * t + 1);
        bar_wait_seq(3 * t + 1);

        // ================= phase 2: D = W2 @ h^T (K-half) ==================
        float d2[4] = {0.f, 0.f, 0.f, 0.f};
        {
            int pg0 = 16 * (b & 1) + 8 * kh;
            const u32* bhp = g_ph + pk(0, nf, pg0, lane);
            const u32* blp = g_ph + pk(1, nf, pg0, lane);
            uint4 Bh = *(const uint4*)bhp;
            uint4 Bl = *(const uint4*)blp;
            #pragma unroll 2
            for (int p = 0; p < 8; ++p) {
                uint4 cBh = Bh, cBl = Bl;
                if (p < 7) {
                    Bh = *(const uint4*)(bhp + (p + 1) * 128);
                    Bl = *(const uint4*)(blp + (p + 1) * 128);
                }
                int kfl0 = 16 * kh + 2 * p;
                u32 Ah0[4], Ah1[4], Al0[4], Al1[4];
                *(uint4*)Ah0 = *(const uint4*)(w2h + ((size_t)kfl0 * 32 + lane) * 4);
                *(uint4*)Ah1 = *(const uint4*)(w2h + ((size_t)(kfl0 + 1) * 32 + lane) * 4);
                *(uint4*)Al0 = *(const uint4*)(w2l + ((size_t)kfl0 * 32 + lane) * 4);
                *(uint4*)Al1 = *(const uint4*)(w2l + ((size_t)(kfl0 + 1) * 32 + lane) * 4);
                mma4(d2, Ah0, cBh.x, cBh.y);
                mma4(d2, Ah0, cBl.x, cBl.y);
                mma4(d2, Al0, cBh.x, cBh.y);
                mma4(d2, Ah1, cBh.z, cBh.w);
                mma4(d2, Ah1, cBl.z, cBl.w);
                mma4(d2, Al1, cBh.z, cBh.w);
            }
        }
        if (wid >= 8)
            *(float4*)&dred[(size_t)((wid - 8) * 32 + lane) * 4] = *(float4*)d2;
        __syncthreads();
        if (wid < 8) {
            float4 o = *(float4*)&dred[(size_t)(wid * 32 + lane) * 4];
            d2[0] += o.x; d2[1] += o.y; d2[2] += o.z; d2[3] += o.w;
            float* gp = g_partB + (size_t)b * 1024;
            *(float2*)(gp + (size_t)gid * 64 + n0)       = make_float2(d2[0], d2[1]);
            *(float2*)(gp + (size_t)(gid + 8) * 64 + n0) = make_float2(d2[2], d2[3]);
        }
        // partner handoff: reduce2 needs only CTAs {b, b^1}
        bar_arrive_seq(b, 3 * t + 2);
        partner_wait_seq(b ^ 1, 3 * t + 2);

        // ================= reduce2: m'-rows 8b..8b+7 =======================
        float v0 = 0.f, v1 = 0.f;
        if (tid < 256) {
            int j = b >> 1;
            int lr0 = 8 * (b & 1) + rr0, lr1 = lr0 + 1;
            v0 = g_partB[(size_t)(2 * j) * 1024 + lr0 * 64 + nn]
               + g_partB[(size_t)(2 * j + 1) * 1024 + lr0 * 64 + nn]
               + g_c2[(size_t)r0g * 64 + nn] + bmv0;
            v1 = g_partB[(size_t)(2 * j) * 1024 + lr1 * 64 + nn]
               + g_partB[(size_t)(2 * j + 1) * 1024 + lr1 * 64 + nn]
               + g_c2[(size_t)r1g * 64 + nn] + bmv1;
            int ln2 = ((nn & 7) << 2) | tg2, nf2 = nn >> 3;
            size_t base = (size_t)((b >> 1) & 1) * 2 + (b & 1);
            g_pm[pk(0, nf2, b >> 2, ln2) + base] = packhi(v0, v1);
            g_pm[pk(1, nf2, b >> 2, ln2) + base] = packlo(v0, v1);
        }
        bar_arrive_seq(b, 3 * t + 3);
        // out[t] store overlaps the full wait (nobody else reads out)
        if (tid < 256) {
            *(float2*)(out + (size_t)t * STEP + (size_t)nn * DIM + r0g) =
                make_float2(v0, v1);
            if (t == T_STEPS - 1)
                *(float2*)(out + OUTS + (size_t)nn * DIM + r0g) =
                    make_float2(v0, v1);
        }
        bar_wait_seq(3 * t + 3);
    }
}

extern "C" void kernel_launch(void* const* d_in, const int* in_sizes, int n_in,
                              void* d_out, int out_size)
{
    const float* x      = (const float*)d_in[0];
    const float* m_prev = (const float*)d_in[1];
    const float* Wxh    = (const float*)d_in[2];
    const float* Whm    = (const float*)d_in[3];
    const float* Wmm    = (const float*)d_in[4];
    const float* Wmh    = (const float*)d_in[5];
    const float* bh     = (const float*)d_in[6];
    const float* bm     = (const float*)d_in[7];
    float* out = (float*)d_out;

    cudaFuncSetAttribute(prologue_mma_k,
                         cudaFuncAttributeMaxDynamicSharedMemorySize, PRO_SMEM);
    cudaFuncSetAttribute(recur_k,
                         cudaFuncAttributeMaxDynamicSharedMemorySize, TC_SMEM);

    zero_flags_k<<<1, 128>>>();
    pack_x_k<<<dim3(128, 512), 512>>>(x);                   // x  -> g_px
    conv_m0_k<<<128, 512>>>(m_prev);                        // m0 -> g_pm
    prologue_mma_k<<<dim3(32, 64), 512, PRO_SMEM>>>(Wxh, bh);  // -> g_xWT
    recur_k<<<128, 512, TC_SMEM>>>(Whm, Wmm, Wmh, bm, out);
}

// round 16
// speedup vs baseline: 1.2694x; 1.2694x over previous
#include <cuda_runtime.h>
#include <cuda_bf16.h>
#include <cstdint>

// LMN layer, round 16 = round-14 recurrence (9.25ms-validated, 3 full
// barriers/step) + round-15 HMMA prologue chain (pack_x + prologue_mma,
// ncu-validated fast). Round-15's partner-wait/out-store-move recur variant
// cost ~5us/step and is reverted.

#define T_STEPS 512
#define DIM     1024
#define STEP    (64 * 1024)
#define OUTS    ((size_t)T_STEPS * STEP)

typedef unsigned long long ull;
typedef uint32_t u32;
typedef uint16_t u16;

__device__ __align__(256) u32   g_px[(size_t)T_STEPS * 65536]; // x packed B-frag
__device__ __align__(256) float g_xWT[(size_t)T_STEPS * STEP]; // [t][feat][batch]
__device__ __align__(256) u32   g_pm[65536];    // m packed [s][nf][pair][lane][4]
__device__ __align__(256) u32   g_ph[65536];    // h packed, same layout
__device__ __align__(256) float g_c2[1024 * 64];
__device__ __align__(256) float g_partB[128 * 16 * 64];
__device__ __align__(128) unsigned g_flags[128 * 32];

// ---------------- bf16 helpers ----------------------------------------------
__device__ __forceinline__ u32 b16(float x) {
    return (u32)__bfloat16_as_ushort(__float2bfloat16(x));
}
__device__ __forceinline__ float fb16(u32 b) {
    return __bfloat162float(__ushort_as_bfloat16((u16)b));
}
__device__ __forceinline__ u32 packlo(float a, float b) {
    float la = a - fb16(b16(a)), lb = b - fb16(b16(b));
    return b16(la) | (b16(lb) << 16);
}
__device__ __forceinline__ u32 packhi(float a, float b) {
    return b16(a) | (b16(b) << 16);
}

// packed activation index: [s][nf][pair(32)][lane(32)][4 u32]
__device__ __forceinline__ size_t pk(int s, int nf, int pair, int lane) {
    return ((((size_t)s * 8 + nf) * 32 + pair) * 32 + lane) * 4;
}

__device__ __forceinline__ void mma4(float* c, const u32* a, u32 b0, u32 b1) {
    asm volatile(
        "mma.sync.aligned.m16n8k16.row.col.f32.bf16.bf16.f32 "
        "{%0,%1,%2,%3}, {%4,%5,%6,%7}, {%8,%9}, {%0,%1,%2,%3};"
        : "+f"(c[0]), "+f"(c[1]), "+f"(c[2]), "+f"(c[3])
        : "r"(a[0]), "r"(a[1]), "r"(a[2]), "r"(a[3]), "r"(b0), "r"(b1));
}

// ---------------- flag-array barrier (128 co-resident CTAs) -----------------
__device__ __forceinline__ void bar_arrive_seq(int b, unsigned seq)
{
    __syncthreads();
    __threadfence();
    if (threadIdx.x == 0)
        asm volatile("st.release.gpu.u32 [%0], %1;"
                     :: "l"(g_flags + (size_t)b * 32), "r"(seq) : "memory");
}
__device__ __forceinline__ void bar_wait_seq(unsigned seq)
{
    if (threadIdx.x < 128) {
        const unsigned* p = g_flags + (size_t)threadIdx.x * 32;
        unsigned v;
        asm volatile("ld.acquire.gpu.u32 %0, [%1];" : "=r"(v) : "l"(p));
        while ((int)(v - seq) < 0) {
            __nanosleep(64);
            asm volatile("ld.acquire.gpu.u32 %0, [%1];" : "=r"(v) : "l"(p));
        }
    }
    __syncthreads();
}
__global__ void zero_flags_k() {
    if (threadIdx.x < 128) g_flags[(size_t)threadIdx.x * 32] = 0u;
}

// ---------------- x -> packed B-frag layout (per t) --------------------------
__global__ void __launch_bounds__(512) pack_x_k(const float* __restrict__ x)
{
    const int t = blockIdx.y;
    int e = blockIdx.x * 512 + threadIdx.x;          // 0..65535
    int q = e & 3, lane = (e >> 2) & 31, pair = (e >> 7) & 31;
    int nf = (e >> 12) & 7, s = e >> 15;
    int kf = 2 * pair + (q >> 1), reg = q & 1;
    int kc = 16 * kf + 2 * (lane & 3) + 8 * reg;
    int n  = 8 * nf + (lane >> 2);
    const float* xs = x + (size_t)t * STEP + (size_t)n * DIM + kc;
    float w0 = xs[0], w1 = xs[1];
    g_px[(size_t)t * 65536 + e] = s ? packlo(w0, w1) : packhi(w0, w1);
}

// ---------------- m0 -> packed B-frag layout --------------------------------
__global__ void conv_m0_k(const float* __restrict__ m_prev)
{
    int e = blockIdx.x * 512 + threadIdx.x;
    int q = e & 3, lane = (e >> 2) & 31, pair = (e >> 7) & 31;
    int nf = (e >> 12) & 7, s = e >> 15;
    int kf = 2 * pair + (q >> 1), reg = q & 1;
    int kc = 16 * kf + 2 * (lane & 3) + 8 * reg;
    int n  = 8 * nf + (lane >> 2);
    float w0 = m_prev[(size_t)n * DIM + kc];
    float w1 = m_prev[(size_t)n * DIM + kc + 1];
    g_pm[e] = s ? packlo(w0, w1) : packhi(w0, w1);
}

// ---------------- HMMA prologue: g_xWT[t] = Wxh @ x[t]^T + bh ---------------
#define P_PAH 0
#define P_PAL 16384
#define P_DRED 32768
#define P_SBH (32768 + 2048)
#define PRO_SMEM ((32768 + 2048 + 32) * 4)     // 139392 B

__global__ void __launch_bounds__(512, 1)
prologue_mma_k(const float* __restrict__ Wxh, const float* __restrict__ bh)
{
    extern __shared__ u32 smu[];
    u32*   pah  = smu + P_PAH;
    u32*   pal  = smu + P_PAL;
    float* dred = (float*)(smu + P_DRED);
    float* sbh  = (float*)(smu + P_SBH);

    const int j = blockIdx.x, tid = threadIdx.x;
    const int wid = tid >> 5, lane = tid & 31;
    const int nf = wid & 7, kh = wid >> 3;
    const int gid = lane >> 2, tig = lane & 3;
    const int n0 = 8 * nf + 2 * tig;

    // pack A (Wxh rows 32j..32j+31) into frag order [fr][kf][lane][4]
    for (int e = tid; e < 16384; e += 512) {
        int reg = e & 3, ln = (e >> 2) & 31, kf = (e >> 7) & 63, fr = e >> 13;
        int row_l = 16 * fr + (ln >> 2) + 8 * (reg & 1);
        int kc    = 16 * kf + 2 * (ln & 3) + 8 * (reg >> 1);
        const float* Ws = Wxh + (size_t)(32 * j + row_l) * DIM + kc;
        float w0 = Ws[0], w1 = Ws[1];
        pah[e] = packhi(w0, w1);
        pal[e] = packlo(w0, w1);
    }
    if (tid < 32) sbh[tid] = bh[32 * j + tid];
    __syncthreads();

    #pragma unroll 1
    for (int tt = 0; tt < 8; ++tt) {
        const int t = blockIdx.y * 8 + tt;
        float c2[2][4] = {{0.f,0.f,0.f,0.f},{0.f,0.f,0.f,0.f}};
        {
            const u32* bhp = g_px + (size_t)t * 65536 + pk(0, nf, 16 * kh, lane);
            const u32* blp = g_px + (size_t)t * 65536 + pk(1, nf, 16 * kh, lane);
            #pragma unroll 2
            for (int p = 0; p < 16; ++p) {
                uint4 Bh = *(const uint4*)(bhp + p * 128);
                uint4 Bl = *(const uint4*)(blp + p * 128);
                int kf0 = 32 * kh + 2 * p;
                #pragma unroll
                for (int half = 0; half < 2; ++half) {
                    u32 bh0 = half ? Bh.z : Bh.x, bh1 = half ? Bh.w : Bh.y;
                    u32 bl0 = half ? Bl.z : Bl.x, bl1 = half ? Bl.w : Bl.y;
                    int kf = kf0 + half;
                    #pragma unroll
                    for (int fr = 0; fr < 2; ++fr) {
                        int ab = ((fr * 64 + kf) * 32 + lane) * 4;
                        u32 Ah[4], Al[4];
                        *(uint4*)Ah = *(const uint4*)(pah + ab);
                        *(uint4*)Al = *(const uint4*)(pal + ab);
                        mma4(c2[fr], Ah, bh0, bh1);
                        mma4(c2[fr], Ah, bl0, bl1);
                        mma4(c2[fr], Al, bh0, bh1);
                    }
                }
            }
        }
        if (kh == 1) {
            #pragma unroll
            for (int fr = 0; fr < 2; ++fr)
                *(float4*)&dred[(size_t)((nf * 2 + fr) * 32 + lane) * 4] =
                    *(float4*)c2[fr];
        }
        __syncthreads();
        if (kh == 0) {
            #pragma unroll
            for (int fr = 0; fr < 2; ++fr) {
                float4 o = *(float4*)&dred[(size_t)((nf * 2 + fr) * 32 + lane) * 4];
                float v0 = c2[fr][0] + o.x, v1 = c2[fr][1] + o.y;
                float v2 = c2[fr][2] + o.z, v3 = c2[fr][3] + o.w;
                int rl0 = 16 * fr + gid, rl1 = rl0 + 8;
                int r0 = 32 * j + rl0, r1 = 32 * j + rl1;
                *(float2*)(g_xWT + (size_t)t * STEP + (size_t)r0 * 64 + n0) =
                    make_float2(v0 + sbh[rl0], v1 + sbh[rl0]);
                *(float2*)(g_xWT + (size_t)t * STEP + (size_t)r1 * 64 + n0) =
                    make_float2(v2 + sbh[rl1], v3 + sbh[rl1]);
            }
        }
        __syncthreads();
    }
}

// ---------------- persistent HMMA recurrence (round-14 structure) -----------
#define SM_W1H 0
#define SM_W1L 8192
#define SM_W2H 16384
#define SM_W2L 20480
#define SM_DRED 24576
#define SM_RP  25600
#define TC_SMEM ((25600 + 1152) * 4)     // 107008 B

__global__ void __launch_bounds__(512, 1)
recur_k(const float* __restrict__ Whm, const float* __restrict__ Wmm,
        const float* __restrict__ Wmh, const float* __restrict__ bm,
        float* __restrict__ out)
{
    extern __shared__ u32 smu[];
    u32*   w1h  = smu + SM_W1H;
    u32*   w1l  = smu + SM_W1L;
    u32*   w2h  = smu + SM_W2H;
    u32*   w2l  = smu + SM_W2L;
    float* dred = (float*)(smu + SM_DRED);
    u16*   rp   = (u16*)(smu + SM_RP);   // [s][16][72]

    const int b = blockIdx.x, tid = threadIdx.x;
    const int wid = tid >> 5, lane = tid & 31;
    const int gid = lane >> 2, tig = lane & 3;
    const int nf = wid & 7, kh = wid >> 3;

    // ---- pack W1 (A-frag order) ----
    for (int e = tid; e < 8192; e += 512) {
        int kf = e >> 7, ln = (e >> 2) & 31, reg = e & 3;
        int row_l = (ln >> 2) + 8 * (reg & 1);
        int kc    = 16 * kf + 2 * (ln & 3) + 8 * (reg >> 1);
        const float* Ws = (b < 64)
            ? (Wmh + (size_t)(16 * b + row_l) * DIM)
            : (Wmm + (size_t)(16 * (b - 64) + row_l) * DIM);
        float w0 = Ws[kc], w1 = Ws[kc + 1];
        w1h[e] = packhi(w0, w1);
        w1l[e] = packlo(w0, w1);
    }
    // ---- pack W2: rows 16*(b>>1), k-half (b&1) ----
    for (int e = tid; e < 4096; e += 512) {
        int kfl = e >> 7, ln = (e >> 2) & 31, reg = e & 3;
        int row_g = 16 * (b >> 1) + (ln >> 2) + 8 * (reg & 1);
        int kc    = 512 * (b & 1) + 16 * kfl + 2 * (ln & 3) + 8 * (reg >> 1);
        float w0 = Whm[(size_t)row_g * DIM + kc];
        float w1 = Whm[(size_t)row_g * DIM + kc + 1];
        w2h[e] = packhi(w0, w1);
        w2l[e] = packlo(w0, w1);
    }
    __syncthreads();

    const int n0 = 8 * nf + 2 * tig;

    #pragma unroll 1
    for (int t = 0; t < T_STEPS; ++t) {
        // ================= phase 1: D = W1 @ m^T (full K) ==================
        float c[4] = {0.f, 0.f, 0.f, 0.f};
        {
            const u32* bhp = g_pm + pk(0, nf, 16 * kh, lane);
            const u32* blp = g_pm + pk(1, nf, 16 * kh, lane);
            uint4 Bh = *(const uint4*)bhp;
            uint4 Bl = *(const uint4*)blp;
            #pragma unroll 2
            for (int p = 0; p < 16; ++p) {
                uint4 cBh = Bh, cBl = Bl;
                if (p < 15) {
                    Bh = *(const uint4*)(bhp + (p + 1) * 128);
                    Bl = *(const uint4*)(blp + (p + 1) * 128);
                }
                int kf0 = 32 * kh + 2 * p;
                u32 Ah0[4], Ah1[4], Al0[4], Al1[4];
                *(uint4*)Ah0 = *(const uint4*)(w1h + ((size_t)kf0 * 32 + lane) * 4);
                *(uint4*)Ah1 = *(const uint4*)(w1h + ((size_t)(kf0 + 1) * 32 + lane) * 4);
                *(uint4*)Al0 = *(const uint4*)(w1l + ((size_t)kf0 * 32 + lane) * 4);
                *(uint4*)Al1 = *(const uint4*)(w1l + ((size_t)(kf0 + 1) * 32 + lane) * 4);
                mma4(c, Ah0, cBh.x, cBh.y);
                mma4(c, Ah0, cBl.x, cBl.y);
                mma4(c, Al0, cBh.x, cBh.y);
                mma4(c, Ah1, cBh.z, cBh.w);
                mma4(c, Ah1, cBl.z, cBl.w);
                mma4(c, Al1, cBh.z, cBh.w);
            }
        }
        if (wid >= 8)
            *(float4*)&dred[(size_t)((wid - 8) * 32 + lane) * 4] = *(float4*)c;
        __syncthreads();
        if (wid < 8) {
            float4 o = *(float4*)&dred[(size_t)(wid * 32 + lane) * 4];
            c[0] += o.x; c[1] += o.y; c[2] += o.z; c[3] += o.w;
            if (b < 64) {
                int f0 = 16 * b + gid;
                ull xa = *(const ull*)(g_xWT + (size_t)t * STEP
                                       + (size_t)f0 * 64 + n0);
                ull xb = *(const ull*)(g_xWT + (size_t)t * STEP
                                       + (size_t)(f0 + 8) * 64 + n0);
                float h0 = tanhf(c[0] + __uint_as_float((u32)xa));
                float h1 = tanhf(c[1] + __uint_as_float((u32)(xa >> 32)));
                float h2 = tanhf(c[2] + __uint_as_float((u32)xb));
                float h3 = tanhf(c[3] + __uint_as_float((u32)(xb >> 32)));
                *(u32*)&rp[(0 * 16 + gid)     * 72 + n0] = packhi(h0, h1);
                *(u32*)&rp[(0 * 16 + gid + 8) * 72 + n0] = packhi(h2, h3);
                *(u32*)&rp[(1 * 16 + gid)     * 72 + n0] = packlo(h0, h1);
                *(u32*)&rp[(1 * 16 + gid + 8) * 72 + n0] = packlo(h2, h3);
            } else {
                int f0 = 16 * (b - 64) + gid;
                *(float2*)(g_c2 + (size_t)f0 * 64 + n0)       =
                    make_float2(c[0], c[1]);
                *(float2*)(g_c2 + (size_t)(f0 + 8) * 64 + n0) =
                    make_float2(c[2], c[3]);
            }
        }
        __syncthreads();
        if (b < 64) {            // repack h -> g_ph (B-frag layout)
            int s  = tid >> 8, q8 = tid & 255;
            int nf2 = q8 >> 5, ln2 = q8 & 31;
            int np = 8 * nf2 + (ln2 >> 2), tg = ln2 & 3;
            u32 v0 = (u32)rp[(s * 16 + 2 * tg)     * 72 + np]
                   | ((u32)rp[(s * 16 + 2 * tg + 1) * 72 + np] << 16);
            u32 v1 = (u32)rp[(s * 16 + 2 * tg + 8) * 72 + np]
                   | ((u32)rp[(s * 16 + 2 * tg + 9) * 72 + np] << 16);
            ull V = (ull)v0 | ((ull)v1 << 32);
            *(ull*)&g_ph[pk(s, nf2, b >> 1, ln2) + (size_t)(b & 1) * 2] = V;
        }
        bar_arrive_seq(b, 3 * t + 1);
        bar_wait_seq(3 * t + 1);

        // ================= phase 2: D = W2 @ h^T (K-half) ==================
        float d2[4] = {0.f, 0.f, 0.f, 0.f};
        {
            int pg0 = 16 * (b & 1) + 8 * kh;
            const u32* bhp = g_ph + pk(0, nf, pg0, lane);
            const u32* blp = g_ph + pk(1, nf, pg0, lane);
            uint4 Bh = *(const uint4*)bhp;
            uint4 Bl = *(const uint4*)blp;
            #pragma unroll 2
            for (int p = 0; p < 8; ++p) {
                uint4 cBh = Bh, cBl = Bl;
                if (p < 7) {
                    Bh = *(const uint4*)(bhp + (p + 1) * 128);
                    Bl = *(const uint4*)(blp + (p + 1) * 128);
                }
                int kfl0 = 16 * kh + 2 * p;
                u32 Ah0[4], Ah1[4], Al0[4], Al1[4];
                *(uint4*)Ah0 = *(const uint4*)(w2h + ((size_t)kfl0 * 32 + lane) * 4);
                *(uint4*)Ah1 = *(const uint4*)(w2h + ((size_t)(kfl0 + 1) * 32 + lane) * 4);
                *(uint4*)Al0 = *(const uint4*)(w2l + ((size_t)kfl0 * 32 + lane) * 4);
                *(uint4*)Al1 = *(const uint4*)(w2l + ((size_t)(kfl0 + 1) * 32 + lane) * 4);
                mma4(d2, Ah0, cBh.x, cBh.y);
                mma4(d2, Ah0, cBl.x, cBl.y);
                mma4(d2, Al0, cBh.x, cBh.y);
                mma4(d2, Ah1, cBh.z, cBh.w);
                mma4(d2, Ah1, cBl.z, cBl.w);
                mma4(d2, Al1, cBh.z, cBh.w);
            }
        }
        if (wid >= 8)
            *(float4*)&dred[(size_t)((wid - 8) * 32 + lane) * 4] = *(float4*)d2;
        __syncthreads();
        if (wid < 8) {
            float4 o = *(float4*)&dred[(size_t)(wid * 32 + lane) * 4];
            d2[0] += o.x; d2[1] += o.y; d2[2] += o.z; d2[3] += o.w;
            float* gp = g_partB + (size_t)b * 1024;
            *(float2*)(gp + (size_t)gid * 64 + n0)       = make_float2(d2[0], d2[1]);
            *(float2*)(gp + (size_t)(gid + 8) * 64 + n0) = make_float2(d2[2], d2[3]);
        }
        bar_arrive_seq(b, 3 * t + 2);
        bar_wait_seq(3 * t + 2);

        // ================= reduce2: m'-rows 8b..8b+7 =======================
        if (tid < 256) {
            int tg2 = tid >> 6, n = tid & 63;
            int rr0 = 2 * tg2, rr1 = rr0 + 1;
            int j = b >> 1;
            int lr0 = 8 * (b & 1) + rr0, lr1 = lr0 + 1;
            int r0 = 8 * b + rr0, r1 = r0 + 1;
            float v0 = g_partB[(size_t)(2 * j) * 1024 + lr0 * 64 + n]
                     + g_partB[(size_t)(2 * j + 1) * 1024 + lr0 * 64 + n]
                     + g_c2[(size_t)r0 * 64 + n] + bm[r0];
            float v1 = g_partB[(size_t)(2 * j) * 1024 + lr1 * 64 + n]
                     + g_partB[(size_t)(2 * j + 1) * 1024 + lr1 * 64 + n]
                     + g_c2[(size_t)r1 * 64 + n] + bm[r1];
            *(float2*)(out + (size_t)t * STEP + (size_t)n * DIM + r0) =
                make_float2(v0, v1);
            if (t == T_STEPS - 1)
                *(float2*)(out + OUTS + (size_t)n * DIM + r0) =
                    make_float2(v0, v1);
            int ln2 = ((n & 7) << 2) | tg2, nf2 = n >> 3;
            size_t base = (size_t)((b >> 1) & 1) * 2 + (b & 1);
            g_pm[pk(0, nf2, b >> 2, ln2) + base] = packhi(v0, v1);
            g_pm[pk(1, nf2, b >> 2, ln2) + base] = packlo(v0, v1);
        }
        bar_arrive_seq(b, 3 * t + 3);
        bar_wait_seq(3 * t + 3);
    }
}

extern "C" void kernel_launch(void* const* d_in, const int* in_sizes, int n_in,
                              void* d_out, int out_size)
{
    const float* x      = (const float*)d_in[0];
    const float* m_prev = (const float*)d_in[1];
    const float* Wxh    = (const float*)d_in[2];
    const float* Whm    = (const float*)d_in[3];
    const float* Wmm    = (const float*)d_in[4];
    const float* Wmh    = (const float*)d_in[5];
    const float* bh     = (const float*)d_in[6];
    const float* bm     = (const float*)d_in[7];
    float* out = (float*)d_out;

    cudaFuncSetAttribute(prologue_mma_k,
                         cudaFuncAttributeMaxDynamicSharedMemorySize, PRO_SMEM);
    cudaFuncSetAttribute(recur_k,
                         cudaFuncAttributeMaxDynamicSharedMemorySize, TC_SMEM);

    zero_flags_k<<<1, 128>>>();
    pack_x_k<<<dim3(128, 512), 512>>>(x);                   // x  -> g_px
    conv_m0_k<<<128, 512>>>(m_prev);                        // m0 -> g_pm
    prologue_mma_k<<<dim3(32, 64), 512, PRO_SMEM>>>(Wxh, bh);  // -> g_xWT
    recur_k<<<128, 512, TC_SMEM>>>(Whm, Wmm, Wmh, bm, out);
}

// round 17
// speedup vs baseline: 1.4625x; 1.1521x over previous
#include <cuda_runtime.h>
#include <cuda_bf16.h>
#include <cstdint>

// LMN layer, round 17 = round 16 with phase2 re-split: N-split (batch) instead
// of K-split. CTA b computes Whm rows 16*(b>>1) x batch 32*(b&1)..+31, FULL K
// -> complete m' values in one pass; epilogue adds c2+bm, writes out + g_pm.
// Removes g_partB round-trip, reduce2 stage, and the 3rd barrier (2 bars/step).
// Phase1 / prologue chain unchanged from round 16 (8.31 ms validated).

#define T_STEPS 512
#define DIM     1024
#define STEP    (64 * 1024)
#define OUTS    ((size_t)T_STEPS * STEP)

typedef unsigned long long ull;
typedef uint32_t u32;
typedef uint16_t u16;

__device__ __align__(256) u32   g_px[(size_t)T_STEPS * 65536]; // x packed B-frag
__device__ __align__(256) float g_xWT[(size_t)T_STEPS * STEP]; // [t][feat][batch]
__device__ __align__(256) u32   g_pm[65536];    // m packed [s][nf][pair][lane][4]
__device__ __align__(256) u32   g_ph[65536];    // h packed, same layout
__device__ __align__(256) float g_c2[1024 * 64];
__device__ __align__(128) unsigned g_flags[128 * 32];

// ---------------- bf16 helpers ----------------------------------------------
__device__ __forceinline__ u32 b16(float x) {
    return (u32)__bfloat16_as_ushort(__float2bfloat16(x));
}
__device__ __forceinline__ float fb16(u32 b) {
    return __bfloat162float(__ushort_as_bfloat16((u16)b));
}
__device__ __forceinline__ u32 packlo(float a, float b) {
    float la = a - fb16(b16(a)), lb = b - fb16(b16(b));
    return b16(la) | (b16(lb) << 16);
}
__device__ __forceinline__ u32 packhi(float a, float b) {
    return b16(a) | (b16(b) << 16);
}

// packed activation index: [s][nf][pair(32)][lane(32)][4 u32]
__device__ __forceinline__ size_t pk(int s, int nf, int pair, int lane) {
    return ((((size_t)s * 8 + nf) * 32 + pair) * 32 + lane) * 4;
}

__device__ __forceinline__ void mma4(float* c, const u32* a, u32 b0, u32 b1) {
    asm volatile(
        "mma.sync.aligned.m16n8k16.row.col.f32.bf16.bf16.f32 "
        "{%0,%1,%2,%3}, {%4,%5,%6,%7}, {%8,%9}, {%0,%1,%2,%3};"
        : "+f"(c[0]), "+f"(c[1]), "+f"(c[2]), "+f"(c[3])
        : "r"(a[0]), "r"(a[1]), "r"(a[2]), "r"(a[3]), "r"(b0), "r"(b1));
}

// ---------------- flag-array barrier (128 co-resident CTAs) -----------------
__device__ __forceinline__ void bar_arrive_seq(int b, unsigned seq)
{
    __syncthreads();
    __threadfence();
    if (threadIdx.x == 0)
        asm volatile("st.release.gpu.u32 [%0], %1;"
                     :: "l"(g_flags + (size_t)b * 32), "r"(seq) : "memory");
}
__device__ __forceinline__ void bar_wait_seq(unsigned seq)
{
    if (threadIdx.x < 128) {
        const unsigned* p = g_flags + (size_t)threadIdx.x * 32;
        unsigned v;
        asm volatile("ld.acquire.gpu.u32 %0, [%1];" : "=r"(v) : "l"(p));
        while ((int)(v - seq) < 0) {
            __nanosleep(64);
            asm volatile("ld.acquire.gpu.u32 %0, [%1];" : "=r"(v) : "l"(p));
        }
    }
    __syncthreads();
}
__global__ void zero_flags_k() {
    if (threadIdx.x < 128) g_flags[(size_t)threadIdx.x * 32] = 0u;
}

// ---------------- x -> packed B-frag layout (per t) --------------------------
__global__ void __launch_bounds__(512) pack_x_k(const float* __restrict__ x)
{
    const int t = blockIdx.y;
    int e = blockIdx.x * 512 + threadIdx.x;          // 0..65535
    int q = e & 3, lane = (e >> 2) & 31, pair = (e >> 7) & 31;
    int nf = (e >> 12) & 7, s = e >> 15;
    int kf = 2 * pair + (q >> 1), reg = q & 1;
    int kc = 16 * kf + 2 * (lane & 3) + 8 * reg;
    int n  = 8 * nf + (lane >> 2);
    const float* xs = x + (size_t)t * STEP + (size_t)n * DIM + kc;
    float w0 = xs[0], w1 = xs[1];
    g_px[(size_t)t * 65536 + e] = s ? packlo(w0, w1) : packhi(w0, w1);
}

// ---------------- m0 -> packed B-frag layout --------------------------------
__global__ void conv_m0_k(const float* __restrict__ m_prev)
{
    int e = blockIdx.x * 512 + threadIdx.x;
    int q = e & 3, lane = (e >> 2) & 31, pair = (e >> 7) & 31;
    int nf = (e >> 12) & 7, s = e >> 15;
    int kf = 2 * pair + (q >> 1), reg = q & 1;
    int kc = 16 * kf + 2 * (lane & 3) + 8 * reg;
    int n  = 8 * nf + (lane >> 2);
    float w0 = m_prev[(size_t)n * DIM + kc];
    float w1 = m_prev[(size_t)n * DIM + kc + 1];
    g_pm[e] = s ? packlo(w0, w1) : packhi(w0, w1);
}

// ---------------- HMMA prologue: g_xWT[t] = Wxh @ x[t]^T + bh ---------------
#define P_PAH 0
#define P_PAL 16384
#define P_DRED 32768
#define P_SBH (32768 + 2048)
#define PRO_SMEM ((32768 + 2048 + 32) * 4)     // 139392 B

__global__ void __launch_bounds__(512, 1)
prologue_mma_k(const float* __restrict__ Wxh, const float* __restrict__ bh)
{
    extern __shared__ u32 smu[];
    u32*   pah  = smu + P_PAH;
    u32*   pal  = smu + P_PAL;
    float* dred = (float*)(smu + P_DRED);
    float* sbh  = (float*)(smu + P_SBH);

    const int j = blockIdx.x, tid = threadIdx.x;
    const int wid = tid >> 5, lane = tid & 31;
    const int nf = wid & 7, kh = wid >> 3;
    const int gid = lane >> 2, tig = lane & 3;
    const int n0 = 8 * nf + 2 * tig;

    for (int e = tid; e < 16384; e += 512) {
        int reg = e & 3, ln = (e >> 2) & 31, kf = (e >> 7) & 63, fr = e >> 13;
        int row_l = 16 * fr + (ln >> 2) + 8 * (reg & 1);
        int kc    = 16 * kf + 2 * (ln & 3) + 8 * (reg >> 1);
        const float* Ws = Wxh + (size_t)(32 * j + row_l) * DIM + kc;
        float w0 = Ws[0], w1 = Ws[1];
        pah[e] = packhi(w0, w1);
        pal[e] = packlo(w0, w1);
    }
    if (tid < 32) sbh[tid] = bh[32 * j + tid];
    __syncthreads();

    #pragma unroll 1
    for (int tt = 0; tt < 8; ++tt) {
        const int t = blockIdx.y * 8 + tt;
        float c2[2][4] = {{0.f,0.f,0.f,0.f},{0.f,0.f,0.f,0.f}};
        {
            const u32* bhp = g_px + (size_t)t * 65536 + pk(0, nf, 16 * kh, lane);
            const u32* blp = g_px + (size_t)t * 65536 + pk(1, nf, 16 * kh, lane);
            #pragma unroll 2
            for (int p = 0; p < 16; ++p) {
                uint4 Bh = *(const uint4*)(bhp + p * 128);
                uint4 Bl = *(const uint4*)(blp + p * 128);
                int kf0 = 32 * kh + 2 * p;
                #pragma unroll
                for (int half = 0; half < 2; ++half) {
                    u32 bh0 = half ? Bh.z : Bh.x, bh1 = half ? Bh.w : Bh.y;
                    u32 bl0 = half ? Bl.z : Bl.x, bl1 = half ? Bl.w : Bl.y;
                    int kf = kf0 + half;
                    #pragma unroll
                    for (int fr = 0; fr < 2; ++fr) {
                        int ab = ((fr * 64 + kf) * 32 + lane) * 4;
                        u32 Ah[4], Al[4];
                        *(uint4*)Ah = *(const uint4*)(pah + ab);
                        *(uint4*)Al = *(const uint4*)(pal + ab);
                        mma4(c2[fr], Ah, bh0, bh1);
                        mma4(c2[fr], Ah, bl0, bl1);
                        mma4(c2[fr], Al, bh0, bh1);
                    }
                }
            }
        }
        if (kh == 1) {
            #pragma unroll
            for (int fr = 0; fr < 2; ++fr)
                *(float4*)&dred[(size_t)((nf * 2 + fr) * 32 + lane) * 4] =
                    *(float4*)c2[fr];
        }
        __syncthreads();
        if (kh == 0) {
            #pragma unroll
            for (int fr = 0; fr < 2; ++fr) {
                float4 o = *(float4*)&dred[(size_t)((nf * 2 + fr) * 32 + lane) * 4];
                float v0 = c2[fr][0] + o.x, v1 = c2[fr][1] + o.y;
                float v2 = c2[fr][2] + o.z, v3 = c2[fr][3] + o.w;
                int rl0 = 16 * fr + gid, rl1 = rl0 + 8;
                int r0 = 32 * j + rl0, r1 = 32 * j + rl1;
                *(float2*)(g_xWT + (size_t)t * STEP + (size_t)r0 * 64 + n0) =
                    make_float2(v0 + sbh[rl0], v1 + sbh[rl0]);
                *(float2*)(g_xWT + (size_t)t * STEP + (size_t)r1 * 64 + n0) =
                    make_float2(v2 + sbh[rl1], v3 + sbh[rl1]);
            }
        }
        __syncthreads();
    }
}

// ---------------- persistent HMMA recurrence --------------------------------
// smem (u32): W1H 8192 | W1L 8192 | W2H 8192 (full K) | W2L 8192 |
//             DRED 2048 f32 | RP u16[2304]
#define SM_W1H 0
#define SM_W1L 8192
#define SM_W2H 16384
#define SM_W2L 24576
#define SM_DRED 32768
#define SM_RP  34816
#define TC_SMEM ((34816 + 1152) * 4)     // 143872 B

__global__ void __launch_bounds__(512, 1)
recur_k(const float* __restrict__ Whm, const float* __restrict__ Wmm,
        const float* __restrict__ Wmh, const float* __restrict__ bm,
        float* __restrict__ out)
{
    extern __shared__ u32 smu[];
    u32*   w1h  = smu + SM_W1H;
    u32*   w1l  = smu + SM_W1L;
    u32*   w2h  = smu + SM_W2H;
    u32*   w2l  = smu + SM_W2L;
    float* dred = (float*)(smu + SM_DRED);
    u16*   rp   = (u16*)(smu + SM_RP);   // [s][16][72]

    const int b = blockIdx.x, tid = threadIdx.x;
    const int wid = tid >> 5, lane = tid & 31;
    const int gid = lane >> 2, tig = lane & 3;
    const int nf = wid & 7, kh = wid >> 3;       // phase-1 roles
    const int nf2 = wid & 3, kh2 = wid >> 2;     // phase-2 roles
    const int jt = b >> 1;                        // phase-2 feature tile

    // ---- pack W1 (A-frag order, 16 rows x full K) ----
    for (int e = tid; e < 8192; e += 512) {
        int kf = e >> 7, ln = (e >> 2) & 31, reg = e & 3;
        int row_l = (ln >> 2) + 8 * (reg & 1);
        int kc    = 16 * kf + 2 * (ln & 3) + 8 * (reg >> 1);
        const float* Ws = (b < 64)
            ? (Wmh + (size_t)(16 * b + row_l) * DIM)
            : (Wmm + (size_t)(16 * (b - 64) + row_l) * DIM);
        float w0 = Ws[kc], w1 = Ws[kc + 1];
        w1h[e] = packhi(w0, w1);
        w1l[e] = packlo(w0, w1);
    }
    // ---- pack W2: rows 16*jt, FULL K (A-frag order) ----
    for (int e = tid; e < 8192; e += 512) {
        int kf = e >> 7, ln = (e >> 2) & 31, reg = e & 3;
        int row_g = 16 * jt + (ln >> 2) + 8 * (reg & 1);
        int kc    = 16 * kf + 2 * (ln & 3) + 8 * (reg >> 1);
        float w0 = Whm[(size_t)row_g * DIM + kc];
        float w1 = Whm[(size_t)row_g * DIM + kc + 1];
        w2h[e] = packhi(w0, w1);
        w2l[e] = packlo(w0, w1);
    }
    __syncthreads();

    const int n0 = 8 * nf + 2 * tig;

    #pragma unroll 1
    for (int t = 0; t < T_STEPS; ++t) {
        // ================= phase 1: D = W1 @ m^T (full K) ==================
        float c[4] = {0.f, 0.f, 0.f, 0.f};
        {
            const u32* bhp = g_pm + pk(0, nf, 16 * kh, lane);
            const u32* blp = g_pm + pk(1, nf, 16 * kh, lane);
            uint4 Bh = *(const uint4*)bhp;
            uint4 Bl = *(const uint4*)blp;
            #pragma unroll 2
            for (int p = 0; p < 16; ++p) {
                uint4 cBh = Bh, cBl = Bl;
                if (p < 15) {
                    Bh = *(const uint4*)(bhp + (p + 1) * 128);
                    Bl = *(const uint4*)(blp + (p + 1) * 128);
                }
                int kf0 = 32 * kh + 2 * p;
                u32 Ah0[4], Ah1[4], Al0[4], Al1[4];
                *(uint4*)Ah0 = *(const uint4*)(w1h + ((size_t)kf0 * 32 + lane) * 4);
                *(uint4*)Ah1 = *(const uint4*)(w1h + ((size_t)(kf0 + 1) * 32 + lane) * 4);
                *(uint4*)Al0 = *(const uint4*)(w1l + ((size_t)kf0 * 32 + lane) * 4);
                *(uint4*)Al1 = *(const uint4*)(w1l + ((size_t)(kf0 + 1) * 32 + lane) * 4);
                mma4(c, Ah0, cBh.x, cBh.y);
                mma4(c, Ah0, cBl.x, cBl.y);
                mma4(c, Al0, cBh.x, cBh.y);
                mma4(c, Ah1, cBh.z, cBh.w);
                mma4(c, Ah1, cBl.z, cBl.w);
                mma4(c, Al1, cBh.z, cBh.w);
            }
        }
        if (wid >= 8)
            *(float4*)&dred[(size_t)((wid - 8) * 32 + lane) * 4] = *(float4*)c;
        __syncthreads();
        if (wid < 8) {
            float4 o = *(float4*)&dred[(size_t)(wid * 32 + lane) * 4];
            c[0] += o.x; c[1] += o.y; c[2] += o.z; c[3] += o.w;
            if (b < 64) {
                int f0 = 16 * b + gid;
                ull xa = *(const ull*)(g_xWT + (size_t)t * STEP
                                       + (size_t)f0 * 64 + n0);
                ull xb = *(const ull*)(g_xWT + (size_t)t * STEP
                                       + (size_t)(f0 + 8) * 64 + n0);
                float h0 = tanhf(c[0] + __uint_as_float((u32)xa));
                float h1 = tanhf(c[1] + __uint_as_float((u32)(xa >> 32)));
                float h2 = tanhf(c[2] + __uint_as_float((u32)xb));
                float h3 = tanhf(c[3] + __uint_as_float((u32)(xb >> 32)));
                *(u32*)&rp[(0 * 16 + gid)     * 72 + n0] = packhi(h0, h1);
                *(u32*)&rp[(0 * 16 + gid + 8) * 72 + n0] = packhi(h2, h3);
                *(u32*)&rp[(1 * 16 + gid)     * 72 + n0] = packlo(h0, h1);
                *(u32*)&rp[(1 * 16 + gid + 8) * 72 + n0] = packlo(h2, h3);
            } else {
                int f0 = 16 * (b - 64) + gid;
                *(float2*)(g_c2 + (size_t)f0 * 64 + n0)       =
                    make_float2(c[0], c[1]);
                *(float2*)(g_c2 + (size_t)(f0 + 8) * 64 + n0) =
                    make_float2(c[2], c[3]);
            }
        }
        __syncthreads();
        if (b < 64) {            // repack h -> g_ph (B-frag layout)
            int s  = tid >> 8, q8 = tid & 255;
            int nfp = q8 >> 5, ln2 = q8 & 31;
            int np = 8 * nfp + (ln2 >> 2), tg = ln2 & 3;
            u32 v0 = (u32)rp[(s * 16 + 2 * tg)     * 72 + np]
                   | ((u32)rp[(s * 16 + 2 * tg + 1) * 72 + np] << 16);
            u32 v1 = (u32)rp[(s * 16 + 2 * tg + 8) * 72 + np]
                   | ((u32)rp[(s * 16 + 2 * tg + 9) * 72 + np] << 16);
            ull V = (ull)v0 | ((ull)v1 << 32);
            *(ull*)&g_ph[pk(s, nfp, b >> 1, ln2) + (size_t)(b & 1) * 2] = V;
        }
        bar_arrive_seq(b, 2 * t + 1);
        bar_wait_seq(2 * t + 1);

        // ===== phase 2: m'[16 rows of tile jt][batch half b&1] = W2@h^T ====
        // warp: nf2 in 0..3 (8-batch frag within the 32-half), kh2 in 0..3
        // (256 k each). Full K per CTA -> complete values after dred reduce.
        float d2[4] = {0.f, 0.f, 0.f, 0.f};
        {
            const int nfg = 4 * (b & 1) + nf2;       // global batch frag
            const u32* bhp = g_ph + pk(0, nfg, 8 * kh2, lane);
            const u32* blp = g_ph + pk(1, nfg, 8 * kh2, lane);
            uint4 Bh = *(const uint4*)bhp;
            uint4 Bl = *(const uint4*)blp;
            #pragma unroll 2
            for (int p = 0; p < 8; ++p) {
                uint4 cBh = Bh, cBl = Bl;
                if (p < 7) {
                    Bh = *(const uint4*)(bhp + (p + 1) * 128);
                    Bl = *(const uint4*)(blp + (p + 1) * 128);
                }
                int kf0 = 16 * kh2 + 2 * p;
                u32 Ah0[4], Ah1[4], Al0[4], Al1[4];
                *(uint4*)Ah0 = *(const uint4*)(w2h + ((size_t)kf0 * 32 + lane) * 4);
                *(uint4*)Ah1 = *(const uint4*)(w2h + ((size_t)(kf0 + 1) * 32 + lane) * 4);
                *(uint4*)Al0 = *(const uint4*)(w2l + ((size_t)kf0 * 32 + lane) * 4);
                *(uint4*)Al1 = *(const uint4*)(w2l + ((size_t)(kf0 + 1) * 32 + lane) * 4);
                mma4(d2, Ah0, cBh.x, cBh.y);
                mma4(d2, Ah0, cBl.x, cBl.y);
                mma4(d2, Al0, cBh.x, cBh.y);
                mma4(d2, Ah1, cBh.z, cBh.w);
                mma4(d2, Ah1, cBl.z, cBl.w);
                mma4(d2, Al1, cBh.z, cBh.w);
            }
        }
        // dred[kh2][nf2][lane][4]
        *(float4*)&dred[(size_t)((kh2 * 4 + nf2) * 32 + lane) * 4] = *(float4*)d2;
        __syncthreads();

        // epilogue: 256 threads, each owns a feature PAIR x one batch col.
        if (tid < 256) {
            int nloc = tid & 31, fp = tid >> 5;       // fl = 2fp, 2fp+1
            int nglob = 32 * (b & 1) + nloc;
            float v[2];
            #pragma unroll
            for (int i = 0; i < 2; ++i) {
                int fl = 2 * fp + i;
                int pl = ((fl & 7) << 2) | ((nloc >> 1) & 3);
                int ci = 2 * (fl >> 3) + (nloc & 1);
                float s = dred[(size_t)((0 * 4 + (nloc >> 3)) * 32 + pl) * 4 + ci]
                        + dred[(size_t)((1 * 4 + (nloc >> 3)) * 32 + pl) * 4 + ci]
                        + dred[(size_t)((2 * 4 + (nloc >> 3)) * 32 + pl) * 4 + ci]
                        + dred[(size_t)((3 * 4 + (nloc >> 3)) * 32 + pl) * 4 + ci];
                int r = 16 * jt + fl;
                v[i] = s + g_c2[(size_t)r * 64 + nglob] + bm[r];
            }
            int r0 = 16 * jt + 2 * fp;
            *(float2*)(out + (size_t)t * STEP + (size_t)nglob * DIM + r0) =
                make_float2(v[0], v[1]);
            if (t == T_STEPS - 1)
                *(float2*)(out + OUTS + (size_t)nglob * DIM + r0) =
                    make_float2(v[0], v[1]);
            // g_pm pack: kf = jt; lane/q per frag convention
            int ln2 = ((nglob & 7) << 2) | (fp & 3);
            size_t base = (size_t)(jt & 1) * 2 + (fp >> 2);
            g_pm[pk(0, nglob >> 3, jt >> 1, ln2) + base] = packhi(v[0], v[1]);
            g_pm[pk(1, nglob >> 3, jt >> 1, ln2) + base] = packlo(v[0], v[1]);
        }
        bar_arrive_seq(b, 2 * t + 2);
        bar_wait_seq(2 * t + 2);
    }
}

extern "C" void kernel_launch(void* const* d_in, const int* in_sizes, int n_in,
                              void* d_out, int out_size)
{
    const float* x      = (const float*)d_in[0];
    const float* m_prev = (const float*)d_in[1];
    const float* Wxh    = (const float*)d_in[2];
    const float* Whm    = (const float*)d_in[3];
    const float* Wmm    = (const float*)d_in[4];
    const float* Wmh    = (const float*)d_in[5];
    const float* bh     = (const float*)d_in[6];
    const float* bm     = (const float*)d_in[7];
    float* out = (float*)d_out;

    cudaFuncSetAttribute(prologue_mma_k,
                         cudaFuncAttributeMaxDynamicSharedMemorySize, PRO_SMEM);
    cudaFuncSetAttribute(recur_k,
                         cudaFuncAttributeMaxDynamicSharedMemorySize, TC_SMEM);

    zero_flags_k<<<1, 128>>>();
    pack_x_k<<<dim3(128, 512), 512>>>(x);                   // x  -> g_px
    conv_m0_k<<<128, 512>>>(m_prev);                        // m0 -> g_pm
    prologue_mma_k<<<dim3(32, 64), 512, PRO_SMEM>>>(Wxh, bh);  // -> g_xWT
    recur_k<<<128, 512, TC_SMEM>>>(Whm, Wmm, Wmh, bm, out);
}